// round 12
// baseline (speedup 1.0000x reference)
#include <cuda_runtime.h>
#include <math.h>

#define NG  3200   // graphs = B*L
#define E   50     // nodes per graph
#define D   100    // embedding dim
#define H   100    // head dim

// Scratch (no allocation allowed in kernel_launch)
__device__ __align__(16) float g_A[D * D];       // A: u[d] = sum_e x0[e]*g_A[e*D+d]
__device__ __align__(16) float g_cp[128];        // Wk @ bq, zero-padded to 128
__device__ __align__(16) float g_bp[128];        // bv + bs, zero-padded to 128
__device__ __align__(16) float g_U[NG * D];      // per-graph u
__device__ __align__(16) float g_wx[NG * 2 * D]; // per-graph packed [w(100) | x0(100)]

// ---------------------------------------------------------------------------
// K1: A = Wk Wq^T (row e per block), block 0 also c = Wk bq and bvs = bv+bs.
// grid = 100 x 128.  Wk staged in smem coalesced (pad-101).
// ---------------------------------------------------------------------------
__global__ void k_pre(const float* __restrict__ Wq, const float* __restrict__ bq,
                      const float* __restrict__ Wk,
                      const float* __restrict__ bv, const float* __restrict__ bs) {
    int b = blockIdx.x, t = threadIdx.x;
    __shared__ float wk[D * 101];   // 40.4KB, pad-101 -> conflict-free rows
    __shared__ float wq[H];
    __shared__ float bqs[H];
    if (t < H) wq[t] = Wq[b * H + t];
    if (b == 0 && t < H) bqs[t] = bq[t];
    for (int i = t; i < D * H; i += 128) {
        int r = i / H, cc = i - r * H;
        wk[r * 101 + cc] = Wk[i];
    }
    __syncthreads();
    if (t < D) {
        float acc = 0.f;
        #pragma unroll 4
        for (int h = 0; h < H; ++h) acc = fmaf(wk[t * 101 + h], wq[h], acc);
        g_A[b * D + t] = acc;
    }
    if (b == 0) {
        float c = 0.f, bb = 0.f;
        if (t < D) {
            #pragma unroll 4
            for (int h = 0; h < H; ++h) c = fmaf(wk[t * 101 + h], bqs[h], c);
            bb = bv[t] + bs[t];
        }
        g_cp[t] = c;   // t in [100,128): zero pad
        g_bp[t] = bb;
    }
}

// ---------------------------------------------------------------------------
// K2: U[g] = c + A x0[g].  CTA = 64 graphs x 32 cols, 128 thr, grid 200.
// Thread = 4 graphs x 4 cols; x tile TRANSPOSED [k][g] so the 4 graphs' x at
// fixed k load as one LDS.128.  2 LDS.128 per 16 FMA -> crossbar unbound.
// ---------------------------------------------------------------------------
__global__ __launch_bounds__(128) void k_u(const int* __restrict__ nid,
                                           const float* __restrict__ emb) {
    __shared__ float As[D * 32];     // [k][c] 12.8KB
    __shared__ float xt[D * 64];     // [k][g] 25.6KB (transposed)
    __shared__ int ids[64];

    int tid = threadIdx.x;
    int bt = blockIdx.x, gt = bt >> 2, ct = bt & 3;
    int gbase = gt * 64, cbase = ct * 32;

    for (int i = tid; i < D * 32; i += 128) {
        int k = i >> 5, col = cbase + (i & 31);
        As[i] = (col < D) ? g_A[k * D + col] : 0.f;
    }
    if (tid < 64) ids[tid] = nid[(gbase + tid) * E];
    __syncthreads();
    for (int q = tid; q < 64 * (D / 4); q += 128) {      // 1600 float4
        int r = q / 25, c = q % 25;
        float4 v = reinterpret_cast<const float4*>(emb)[ids[r] * (D / 4) + c];
        xt[(c * 4 + 0) * 64 + r] = v.x;
        xt[(c * 4 + 1) * 64 + r] = v.y;
        xt[(c * 4 + 2) * 64 + r] = v.z;
        xt[(c * 4 + 3) * 64 + r] = v.w;
    }
    __syncthreads();

    int hq = tid & 7, gq = tid >> 3;     // 8 h-groups x 16 g-groups
    int h0 = hq * 4, g0 = gq * 4;
    int hglob = cbase + h0;

    float4 b4 = *reinterpret_cast<const float4*>(&g_cp[hglob]);
    float4 a0 = b4, a1 = b4, a2 = b4, a3 = b4;
    #pragma unroll 4
    for (int k = 0; k < D; ++k) {
        float4 w = *reinterpret_cast<const float4*>(&As[k * 32 + h0]);
        float4 x = *reinterpret_cast<const float4*>(&xt[k * 64 + g0]);
        a0.x = fmaf(x.x, w.x, a0.x); a0.y = fmaf(x.x, w.y, a0.y);
        a0.z = fmaf(x.x, w.z, a0.z); a0.w = fmaf(x.x, w.w, a0.w);
        a1.x = fmaf(x.y, w.x, a1.x); a1.y = fmaf(x.y, w.y, a1.y);
        a1.z = fmaf(x.y, w.z, a1.z); a1.w = fmaf(x.y, w.w, a1.w);
        a2.x = fmaf(x.z, w.x, a2.x); a2.y = fmaf(x.z, w.y, a2.y);
        a2.z = fmaf(x.z, w.z, a2.z); a2.w = fmaf(x.z, w.w, a2.w);
        a3.x = fmaf(x.w, w.x, a3.x); a3.y = fmaf(x.w, w.y, a3.y);
        a3.z = fmaf(x.w, w.z, a3.z); a3.w = fmaf(x.w, w.w, a3.w);
    }
    if (hglob < H) {
        float* up = &g_U[(gbase + g0) * D + hglob];
        *reinterpret_cast<float4*>(up)         = a0;
        *reinterpret_cast<float4*>(up + D)     = a1;
        *reinterpret_cast<float4*>(up + 2 * D) = a2;
        *reinterpret_cast<float4*>(up + 3 * D) = a3;
    }
}

// ---------------------------------------------------------------------------
// K3: per-graph attention, parallel ballot compaction. 1 CTA/graph, 128 thr.
// ---------------------------------------------------------------------------
__global__ __launch_bounds__(128) void k_attn(const int* __restrict__ nid,
                                              const int* __restrict__ adj,
                                              const float* __restrict__ emb) {
    constexpr int LD = 101;
    __shared__ float X[E * LD];
    __shared__ float u_s[D];
    __shared__ float sc[E];
    __shared__ float ps[E];
    __shared__ int ids[E];
    __shared__ unsigned bal[2];
    __shared__ int cnt_s;

    int g = blockIdx.x, tid = threadIdx.x;
    int warp = tid >> 5, lane = tid & 31;

    int myid = 0, m = 0;
    if (tid < E) {
        myid = nid[g * E + tid];
        m    = adj[g * (E * E) + tid * E];   // edge j -> node 0
    }
    if (tid < D) u_s[tid] = g_U[g * D + tid];

    unsigned bw = __ballot_sync(0xffffffffu, m != 0);
    if (warp < 2 && lane == 0) bal[warp] = bw;
    __syncthreads();
    unsigned b0 = bal[0], b1 = bal[1];
    int cnt = __popc(b0) + __popc(b1);
    if (tid == 0) cnt_s = cnt;
    if (tid < E && m) {
        int pos = __popc((warp ? b0 : 0u)) +
                  __popc((warp ? b1 : b0) & ((1u << lane) - 1u));
        ids[pos] = myid;
    }
    __syncthreads();
    cnt = cnt_s;

    for (int q = tid; q < cnt * (D / 4); q += 128) {
        int r = q / 25, cc = q % 25;
        float4 v = reinterpret_cast<const float4*>(emb)[ids[r] * (D / 4) + cc];
        float* dst = &X[r * LD + cc * 4];
        dst[0] = v.x; dst[1] = v.y; dst[2] = v.z; dst[3] = v.w;
    }
    __syncthreads();

    if (tid < cnt) {
        const float* xr = &X[tid * LD];
        float s0 = 0.f, s1 = 0.f;
        #pragma unroll 10
        for (int d2 = 0; d2 < D; d2 += 2) {
            s0 = fmaf(xr[d2],     u_s[d2],     s0);
            s1 = fmaf(xr[d2 + 1], u_s[d2 + 1], s1);
        }
        sc[tid] = (s0 + s1) * 0.1f;          // /sqrt(H)
    }
    __syncthreads();

    float mx = -1e30f;
    for (int j = 0; j < cnt; ++j) mx = fmaxf(mx, sc[j]);
    if (tid < cnt) ps[tid] = __expf(sc[tid] - mx);
    __syncthreads();

    float S = 0.f;
    for (int j = 0; j < cnt; ++j) S += ps[j];
    float inv = 1.0f / S;

    if (tid < D) {
        float w = 0.f;
        for (int j = 0; j < cnt; ++j) w = fmaf(ps[j], X[j * LD + tid], w);
        g_wx[g * (2 * D) + tid]     = w * inv;
        g_wx[g * (2 * D) + D + tid] = X[tid];   // compact row 0 = x0
    }
}

// ---------------------------------------------------------------------------
// K4: out[g] = bvs + [w|x0] @ [Wv;Ws].  CTA = 64 g x 32 c, 128 thr, grid 200.
// Thread = 4 graphs x 4 cols; wx tile transposed [k][g]; K=200.
// ---------------------------------------------------------------------------
__global__ __launch_bounds__(128) void k_out(const float* __restrict__ Wv,
                                             const float* __restrict__ Ws,
                                             float* __restrict__ out) {
    extern __shared__ float smo[];
    float* Wcs = smo;                // [200][32] 25.6KB
    float* xt  = smo + 2 * D * 32;   // [200][64] 51.2KB (transposed)

    int tid = threadIdx.x;
    int bt = blockIdx.x, gt = bt >> 2, ct = bt & 3;
    int gbase = gt * 64, cbase = ct * 32;

    for (int i4 = tid; i4 < 2 * D * 8; i4 += 128) {      // 1600 float4
        int k = i4 >> 3, col = cbase + (i4 & 7) * 4;
        float4 v = make_float4(0.f, 0.f, 0.f, 0.f);
        if (col < H) {
            const float* src = (k < D) ? &Wv[k * H + col] : &Ws[(k - D) * H + col];
            v = *reinterpret_cast<const float4*>(src);
        }
        *reinterpret_cast<float4*>(&Wcs[k * 32 + (i4 & 7) * 4]) = v;
    }
    for (int q = tid; q < 64 * (2 * D / 4); q += 128) {  // 3200 float4, coalesced
        int r = q / 50, c = q % 50;
        float4 v = reinterpret_cast<const float4*>(g_wx)[(gbase + r) * 50 + c];
        xt[(c * 4 + 0) * 64 + r] = v.x;
        xt[(c * 4 + 1) * 64 + r] = v.y;
        xt[(c * 4 + 2) * 64 + r] = v.z;
        xt[(c * 4 + 3) * 64 + r] = v.w;
    }
    __syncthreads();

    int hq = tid & 7, gq = tid >> 3;
    int h0 = hq * 4, g0 = gq * 4;
    int hglob = cbase + h0;

    float4 b4 = *reinterpret_cast<const float4*>(&g_bp[hglob]);
    float4 a0 = b4, a1 = b4, a2 = b4, a3 = b4;
    #pragma unroll 4
    for (int k = 0; k < 2 * D; ++k) {
        float4 w = *reinterpret_cast<const float4*>(&Wcs[k * 32 + h0]);
        float4 x = *reinterpret_cast<const float4*>(&xt[k * 64 + g0]);
        a0.x = fmaf(x.x, w.x, a0.x); a0.y = fmaf(x.x, w.y, a0.y);
        a0.z = fmaf(x.x, w.z, a0.z); a0.w = fmaf(x.x, w.w, a0.w);
        a1.x = fmaf(x.y, w.x, a1.x); a1.y = fmaf(x.y, w.y, a1.y);
        a1.z = fmaf(x.y, w.z, a1.z); a1.w = fmaf(x.y, w.w, a1.w);
        a2.x = fmaf(x.z, w.x, a2.x); a2.y = fmaf(x.z, w.y, a2.y);
        a2.z = fmaf(x.z, w.z, a2.z); a2.w = fmaf(x.z, w.w, a2.w);
        a3.x = fmaf(x.w, w.x, a3.x); a3.y = fmaf(x.w, w.y, a3.y);
        a3.z = fmaf(x.w, w.z, a3.z); a3.w = fmaf(x.w, w.w, a3.w);
    }
    if (hglob < H) {
        float* op = &out[(gbase + g0) * H + hglob];
        *reinterpret_cast<float4*>(op)         = a0;
        *reinterpret_cast<float4*>(op + H)     = a1;
        *reinterpret_cast<float4*>(op + 2 * H) = a2;
        *reinterpret_cast<float4*>(op + 3 * H) = a3;
    }
}

// ---------------------------------------------------------------------------
extern "C" void kernel_launch(void* const* d_in, const int* in_sizes, int n_in,
                              void* d_out, int out_size) {
    const int*   nid = (const int*)d_in[0];
    const int*   adj = (const int*)d_in[1];
    const float* emb = (const float*)d_in[2];
    const float* Wq  = (const float*)d_in[3];
    const float* bq  = (const float*)d_in[4];
    const float* Wk  = (const float*)d_in[5];
    // d_in[6] = bk: cancels in softmax (constant per-row shift)
    const float* Wv  = (const float*)d_in[7];
    const float* bv  = (const float*)d_in[8];
    const float* Ws  = (const float*)d_in[9];
    const float* bs  = (const float*)d_in[10];
    float* out = (float*)d_out;

    const int smemO = (2 * D * 32 + 2 * D * 64) * (int)sizeof(float);  // 76.8KB
    cudaFuncSetAttribute(k_out, cudaFuncAttributeMaxDynamicSharedMemorySize, smemO);

    k_pre<<<D, 128>>>(Wq, bq, Wk, bv, bs);
    k_u<<<200, 128>>>(nid, emb);
    k_attn<<<NG, 128>>>(nid, adj, emb);
    k_out<<<200, 128, smemO>>>(Wv, Ws, out);
}

// round 13
// speedup vs baseline: 1.1770x; 1.1770x over previous
#include <cuda_runtime.h>
#include <math.h>

#define NG  3200   // graphs = B*L
#define E   50     // nodes per graph
#define D   100    // embedding dim
#define H   100    // head dim

// Scratch (no allocation allowed in kernel_launch)
__device__ __align__(16) float g_A[D * D];       // A: u[d] = sum_e x0[e]*g_A[e*D+d]
__device__ __align__(16) float g_cp[128];        // Wk @ bq, zero-padded to 128
__device__ __align__(16) float g_bp[128];        // bv + bs, zero-padded to 128
__device__ __align__(16) float g_U[NG * D];      // per-graph u
__device__ __align__(16) float g_wx[NG * 2 * D]; // per-graph packed [w(100) | x0(100)]

// ---------------------------------------------------------------------------
// K1: A = Wk Wq^T (row e per block), block 0 also c = Wk bq and bvs = bv+bs.
// grid = 100 x 128.  Wk staged in smem coalesced (pad-101).
// ---------------------------------------------------------------------------
__global__ void k_pre(const float* __restrict__ Wq, const float* __restrict__ bq,
                      const float* __restrict__ Wk,
                      const float* __restrict__ bv, const float* __restrict__ bs) {
    int b = blockIdx.x, t = threadIdx.x;
    __shared__ float wk[D * 101];   // 40.4KB, pad-101 -> conflict-free rows
    __shared__ float wq[H];
    __shared__ float bqs[H];
    if (t < H) wq[t] = Wq[b * H + t];
    if (b == 0 && t < H) bqs[t] = bq[t];
    for (int i = t; i < D * H; i += 128) {
        int r = i / H, cc = i - r * H;
        wk[r * 101 + cc] = Wk[i];
    }
    __syncthreads();
    if (t < D) {
        float acc = 0.f;
        #pragma unroll 4
        for (int h = 0; h < H; ++h) acc = fmaf(wk[t * 101 + h], wq[h], acc);
        g_A[b * D + t] = acc;
    }
    if (b == 0) {
        float c = 0.f, bb = 0.f;
        if (t < D) {
            #pragma unroll 4
            for (int h = 0; h < H; ++h) c = fmaf(wk[t * 101 + h], bqs[h], c);
            bb = bv[t] + bs[t];
        }
        g_cp[t] = c;   // t in [100,128): zero pad
        g_bp[t] = bb;
    }
}

// ---------------------------------------------------------------------------
// K2: U[g] = c + A x0[g].  CTA = 32 graphs x 64 cols, 256 thr, grid 200.
// Thread = 2 graphs x 4 cols.  38.4KB smem -> 5 CTAs/SM, 40 warps/SM.
// Per k: 1 LDS.128 (w, 2wf) + 2 LDS.32 (x, bcast, 1wf ea) + 8 FMA.
// ---------------------------------------------------------------------------
__global__ __launch_bounds__(256) void k_u(const int* __restrict__ nid,
                                           const float* __restrict__ emb) {
    __shared__ float As[D * 64];     // [k][c] 25.6KB
    __shared__ float xs[32 * D];     // [g][k] 12.8KB
    __shared__ int ids[32];

    int tid = threadIdx.x;
    int bt = blockIdx.x, gt = bt >> 1, ct = bt & 1;
    int gbase = gt * 32, cbase = ct * 64;

    if (tid < 32) ids[tid] = nid[(gbase + tid) * E];
    for (int i4 = tid; i4 < D * 16; i4 += 256) {         // 1600 float4
        int k = i4 >> 4, lc = (i4 & 15) * 4, col = cbase + lc;
        float4 v = make_float4(0.f, 0.f, 0.f, 0.f);
        if (col < D) v = *reinterpret_cast<const float4*>(&g_A[k * D + col]);
        *reinterpret_cast<float4*>(&As[k * 64 + lc]) = v;
    }
    __syncthreads();
    for (int q = tid; q < 32 * (D / 4); q += 256) {      // 800 float4, coalesced
        int r = q / 25, c = q % 25;
        reinterpret_cast<float4*>(&xs[r * D])[c] =
            reinterpret_cast<const float4*>(emb)[ids[r] * (D / 4) + c];
    }
    __syncthreads();

    int hq = tid & 15, gq = tid >> 4;    // 16 h-groups x 16 g-groups
    int h0 = hq * 4, g0 = gq * 2;
    int hglob = cbase + h0;
    const float* x0r = &xs[g0 * D];
    const float* x1r = x0r + D;

    float4 a0 = *reinterpret_cast<const float4*>(&g_cp[hglob]);
    float4 a1 = a0;
    #pragma unroll 4
    for (int k = 0; k < D; ++k) {
        float4 w = *reinterpret_cast<const float4*>(&As[k * 64 + h0]);
        float xa = x0r[k], xb = x1r[k];
        a0.x = fmaf(xa, w.x, a0.x); a0.y = fmaf(xa, w.y, a0.y);
        a0.z = fmaf(xa, w.z, a0.z); a0.w = fmaf(xa, w.w, a0.w);
        a1.x = fmaf(xb, w.x, a1.x); a1.y = fmaf(xb, w.y, a1.y);
        a1.z = fmaf(xb, w.z, a1.z); a1.w = fmaf(xb, w.w, a1.w);
    }
    if (hglob < H) {
        float* up = &g_U[(gbase + g0) * D + hglob];
        *reinterpret_cast<float4*>(up)     = a0;
        *reinterpret_cast<float4*>(up + D) = a1;
    }
}

// ---------------------------------------------------------------------------
// K3: per-graph attention, parallel ballot compaction. 1 CTA/graph, 128 thr.
// ---------------------------------------------------------------------------
__global__ __launch_bounds__(128) void k_attn(const int* __restrict__ nid,
                                              const int* __restrict__ adj,
                                              const float* __restrict__ emb) {
    constexpr int LD = 101;
    __shared__ float X[E * LD];
    __shared__ float u_s[D];
    __shared__ float sc[E];
    __shared__ float ps[E];
    __shared__ int ids[E];
    __shared__ unsigned bal[2];
    __shared__ int cnt_s;

    int g = blockIdx.x, tid = threadIdx.x;
    int warp = tid >> 5, lane = tid & 31;

    int myid = 0, m = 0;
    if (tid < E) {
        myid = nid[g * E + tid];
        m    = adj[g * (E * E) + tid * E];   // edge j -> node 0
    }
    if (tid < D) u_s[tid] = g_U[g * D + tid];

    unsigned bw = __ballot_sync(0xffffffffu, m != 0);
    if (warp < 2 && lane == 0) bal[warp] = bw;
    __syncthreads();
    unsigned b0 = bal[0], b1 = bal[1];
    int cnt = __popc(b0) + __popc(b1);
    if (tid == 0) cnt_s = cnt;
    if (tid < E && m) {
        int pos = __popc((warp ? b0 : 0u)) +
                  __popc((warp ? b1 : b0) & ((1u << lane) - 1u));
        ids[pos] = myid;
    }
    __syncthreads();
    cnt = cnt_s;

    for (int q = tid; q < cnt * (D / 4); q += 128) {
        int r = q / 25, cc = q % 25;
        float4 v = reinterpret_cast<const float4*>(emb)[ids[r] * (D / 4) + cc];
        float* dst = &X[r * LD + cc * 4];
        dst[0] = v.x; dst[1] = v.y; dst[2] = v.z; dst[3] = v.w;
    }
    __syncthreads();

    if (tid < cnt) {
        const float* xr = &X[tid * LD];
        float s0 = 0.f, s1 = 0.f;
        #pragma unroll 10
        for (int d2 = 0; d2 < D; d2 += 2) {
            s0 = fmaf(xr[d2],     u_s[d2],     s0);
            s1 = fmaf(xr[d2 + 1], u_s[d2 + 1], s1);
        }
        sc[tid] = (s0 + s1) * 0.1f;          // /sqrt(H)
    }
    __syncthreads();

    float mx = -1e30f;
    for (int j = 0; j < cnt; ++j) mx = fmaxf(mx, sc[j]);
    if (tid < cnt) ps[tid] = __expf(sc[tid] - mx);
    __syncthreads();

    float S = 0.f;
    for (int j = 0; j < cnt; ++j) S += ps[j];
    float inv = 1.0f / S;

    if (tid < D) {
        float w = 0.f;
        for (int j = 0; j < cnt; ++j) w = fmaf(ps[j], X[j * LD + tid], w);
        g_wx[g * (2 * D) + tid]     = w * inv;
        g_wx[g * (2 * D) + D + tid] = X[tid];   // compact row 0 = x0
    }
}

// ---------------------------------------------------------------------------
// K4: out[g] = bvs + [w|x0] @ [Wv;Ws].  CTA = 32 g x 64 c, 256 thr, grid 200.
// Thread = 2 graphs x 4 cols, K=200.  76.8KB smem -> 2 CTAs/SM, 16 warps/SM.
// ---------------------------------------------------------------------------
__global__ __launch_bounds__(256) void k_out(const float* __restrict__ Wv,
                                             const float* __restrict__ Ws,
                                             float* __restrict__ out) {
    extern __shared__ float smo[];
    float* Wcs = smo;                // [200][64] 51.2KB
    float* xs  = smo + 2 * D * 64;   // [32][200] 25.6KB

    int tid = threadIdx.x;
    int bt = blockIdx.x, gt = bt >> 1, ct = bt & 1;
    int gbase = gt * 32, cbase = ct * 64;

    for (int i4 = tid; i4 < 2 * D * 16; i4 += 256) {     // 3200 float4
        int k = i4 >> 4, lc = (i4 & 15) * 4, col = cbase + lc;
        float4 v = make_float4(0.f, 0.f, 0.f, 0.f);
        if (col < H) {
            const float* src = (k < D) ? &Wv[k * H + col] : &Ws[(k - D) * H + col];
            v = *reinterpret_cast<const float4*>(src);
        }
        *reinterpret_cast<float4*>(&Wcs[k * 64 + lc]) = v;
    }
    for (int q = tid; q < 32 * (2 * D / 4); q += 256)    // 1600 float4, coalesced
        reinterpret_cast<float4*>(xs)[q] =
            reinterpret_cast<const float4*>(g_wx)[gbase * (2 * D / 4) + q];
    __syncthreads();

    int hq = tid & 15, gq = tid >> 4;
    int h0 = hq * 4, g0 = gq * 2;
    int hglob = cbase + h0;
    const float* x0r = &xs[g0 * 2 * D];
    const float* x1r = x0r + 2 * D;

    float4 a0 = *reinterpret_cast<const float4*>(&g_bp[hglob]);
    float4 a1 = a0;
    #pragma unroll 4
    for (int k = 0; k < 2 * D; ++k) {
        float4 w = *reinterpret_cast<const float4*>(&Wcs[k * 64 + h0]);
        float xa = x0r[k], xb = x1r[k];
        a0.x = fmaf(xa, w.x, a0.x); a0.y = fmaf(xa, w.y, a0.y);
        a0.z = fmaf(xa, w.z, a0.z); a0.w = fmaf(xa, w.w, a0.w);
        a1.x = fmaf(xb, w.x, a1.x); a1.y = fmaf(xb, w.y, a1.y);
        a1.z = fmaf(xb, w.z, a1.z); a1.w = fmaf(xb, w.w, a1.w);
    }
    if (hglob < H) {
        float* op = &out[(gbase + g0) * H + hglob];
        *reinterpret_cast<float4*>(op)     = a0;
        *reinterpret_cast<float4*>(op + H) = a1;
    }
}

// ---------------------------------------------------------------------------
extern "C" void kernel_launch(void* const* d_in, const int* in_sizes, int n_in,
                              void* d_out, int out_size) {
    const int*   nid = (const int*)d_in[0];
    const int*   adj = (const int*)d_in[1];
    const float* emb = (const float*)d_in[2];
    const float* Wq  = (const float*)d_in[3];
    const float* bq  = (const float*)d_in[4];
    const float* Wk  = (const float*)d_in[5];
    // d_in[6] = bk: cancels in softmax (constant per-row shift)
    const float* Wv  = (const float*)d_in[7];
    const float* bv  = (const float*)d_in[8];
    const float* Ws  = (const float*)d_in[9];
    const float* bs  = (const float*)d_in[10];
    float* out = (float*)d_out;

    const int smemO = (2 * D * 64 + 32 * 2 * D) * (int)sizeof(float);  // 76.8KB
    cudaFuncSetAttribute(k_out, cudaFuncAttributeMaxDynamicSharedMemorySize, smemO);

    k_pre<<<D, 128>>>(Wq, bq, Wk, bv, bs);
    k_u<<<200, 256>>>(nid, emb);
    k_attn<<<NG, 128>>>(nid, adj, emb);
    k_out<<<200, 256, smemO>>>(Wv, Ws, out);
}